// round 5
// baseline (speedup 1.0000x reference)
#include <cuda_runtime.h>
#include <cstdint>

#define DEVINL __device__ __forceinline__

static constexpr int B_ = 32, N_ = 256, T_ = 1024, O_ = 1024, G_ = 8;

// 128 MB scratch for w_bot[b][o][t] (tf32-rounded fp32). Static __device__
// array per harness allocation rules.
__device__ float g_wbot[(size_t)B_ * O_ * T_];

// ---------------- helpers ----------------
DEVINL uint32_t smem_u32(const void* p) {
    uint32_t a;
    asm("{ .reg .u64 t; cvta.to.shared.u64 t, %1; cvt.u32.u64 %0, t; }" : "=r"(a) : "l"(p));
    return a;
}
DEVINL void cp_async16(uint32_t d, const void* g) {
    asm volatile("cp.async.cg.shared.global [%0], [%1], 16;" :: "r"(d), "l"(g) : "memory");
}
DEVINL void cp_commit() { asm volatile("cp.async.commit_group;" ::: "memory"); }
template <int NPend> DEVINL void cp_wait() {
    asm volatile("cp.async.wait_group %0;" :: "n"(NPend) : "memory");
}
DEVINL uint32_t tf32_rna_bits(float x) {
    uint32_t u;
    asm("cvt.rna.tf32.f32 %0, %1;" : "=r"(u) : "f"(x));
    return u;
}
DEVINL void mma_tf32(float& c0, float& c1, float& c2, float& c3,
                     uint32_t a0, uint32_t a1, uint32_t a2, uint32_t a3,
                     uint32_t b0, uint32_t b1) {
    asm volatile(
        "mma.sync.aligned.m16n8k8.row.col.f32.tf32.tf32.f32 "
        "{%0,%1,%2,%3}, {%4,%5,%6,%7}, {%8,%9}, {%0,%1,%2,%3};"
        : "+f"(c0), "+f"(c1), "+f"(c2), "+f"(c3)
        : "r"(a0), "r"(a1), "r"(a2), "r"(a3), "r"(b0), "r"(b1));
}

// ---------------- Pass 1: genre mixing ----------------
// w_bot[b,o,t] = sum_g y[b,g] * weight[g,o,t] * mask[o,t], rounded rna->tf32.
__global__ void __launch_bounds__(256) mix_kernel(const float* __restrict__ y,
                                                  const float* __restrict__ weight,
                                                  const float* __restrict__ mask) {
    __shared__ float ys[B_ * G_];  // 256
    const int tid = threadIdx.x;
    ys[tid] = y[tid];
    __syncthreads();

    const int idx = blockIdx.x * 256 + tid;  // over O*T/4
    const float4 mv = reinterpret_cast<const float4*>(mask)[idx];
    float4 wm[G_];
#pragma unroll
    for (int g = 0; g < G_; g++) {
        float4 w = reinterpret_cast<const float4*>(weight)[(size_t)g * (O_ * T_ / 4) + idx];
        wm[g].x = w.x * mv.x; wm[g].y = w.y * mv.y;
        wm[g].z = w.z * mv.z; wm[g].w = w.w * mv.w;
    }
    float4* wb = reinterpret_cast<float4*>(g_wbot) + idx;
#pragma unroll 4
    for (int b = 0; b < B_; b++) {
        float4 a = make_float4(0.f, 0.f, 0.f, 0.f);
#pragma unroll
        for (int g = 0; g < G_; g++) {
            const float yv = ys[b * G_ + g];
            a.x = fmaf(yv, wm[g].x, a.x);
            a.y = fmaf(yv, wm[g].y, a.y);
            a.z = fmaf(yv, wm[g].z, a.z);
            a.w = fmaf(yv, wm[g].w, a.w);
        }
        a.x = __uint_as_float(tf32_rna_bits(a.x));
        a.y = __uint_as_float(tf32_rna_bits(a.y));
        a.z = __uint_as_float(tf32_rna_bits(a.z));
        a.w = __uint_as_float(tf32_rna_bits(a.w));
        wb[(size_t)b * (O_ * T_ / 4)] = a;
    }
}

// ---------------- Pass 2: batched tf32 GEMM (mma.sync, sm_80 path) ----------
// out[b, m, o] = sum_t x[b,m,t] * w_bot[b,o,t] + bias[o]
// CTA tile: M=128 (rows of x), N=128 (rows of w_bot = output cols), BK=32.
// 8 warps: warp grid 2(m) x 4(n), warp tile 64x32. mma m16n8k8 tf32.
static constexpr int BM = 128, BN = 128, BK = 32, STAGES = 4;
static constexpr int LDSR = 36;                         // padded row: 32 + 4 floats
static constexpr int STAGE_FLOATS = (BM + BN) * LDSR;   // 9216 floats = 36 KB
static constexpr int NKT = T_ / BK;                     // 32 k-tiles
static constexpr uint32_t SMEM_BYTES = STAGES * STAGE_FLOATS * 4;  // 147456

DEVINL void load_stage(float* st, const float* __restrict__ gA,
                       const float* __restrict__ gB, int tid) {
    // A: 128 rows x 32 floats (8 x 16B chunks per row) = 1024 chunks
    float* sA = st;
    float* sB = st + BM * LDSR;
#pragma unroll
    for (int i = 0; i < 4; i++) {
        const int v = tid + i * 256;
        const int row = v >> 3, c = v & 7;
        cp_async16(smem_u32(sA + row * LDSR + c * 4), gA + (size_t)row * T_ + c * 4);
    }
#pragma unroll
    for (int i = 0; i < 4; i++) {
        const int v = tid + i * 256;
        const int row = v >> 3, c = v & 7;
        cp_async16(smem_u32(sB + row * LDSR + c * 4), gB + (size_t)row * T_ + c * 4);
    }
}

__global__ void __launch_bounds__(256, 1)
gemm_kernel(const float* __restrict__ x, const float* __restrict__ bias,
            float* __restrict__ out) {
    extern __shared__ float smem[];
    const int tid = threadIdx.x;
    const int wid = tid >> 5, lane = tid & 31;
    const int lq = lane >> 2, lr = lane & 3;  // quad row, quad col
    const int wm = wid & 1, wn = wid >> 1;    // warp m (0..1), warp n (0..3)
    const int b = blockIdx.z;
    const int o0 = blockIdx.x * BN;
    const int m0 = blockIdx.y * BM;

    const float* gA = x + ((size_t)b * N_ + m0) * T_;            // [128, T]
    const float* gB = g_wbot + ((size_t)b * O_ + o0) * T_;       // [128, T]

    float acc[4][4][4];
#pragma unroll
    for (int i = 0; i < 4; i++)
#pragma unroll
        for (int j = 0; j < 4; j++)
#pragma unroll
            for (int k = 0; k < 4; k++) acc[i][j][k] = 0.f;

    // Prologue: fill stages 0..2
#pragma unroll
    for (int s = 0; s < STAGES - 1; s++) {
        load_stage(smem + s * STAGE_FLOATS, gA + s * BK, gB + s * BK, tid);
        cp_commit();
    }

    const int m_base = wm * 64;
    const int n_base = wn * 32;

    for (int kt = 0; kt < NKT; kt++) {
        cp_wait<STAGES - 2>();
        __syncthreads();

        // Issue next stage load (overlaps with compute below)
        if (kt + STAGES - 1 < NKT) {
            const int kn = kt + STAGES - 1;
            load_stage(smem + (kn % STAGES) * STAGE_FLOATS,
                       gA + (size_t)kn * BK, gB + (size_t)kn * BK, tid);
        }
        cp_commit();

        const float* sA = smem + (kt % STAGES) * STAGE_FLOATS;
        const float* sB = sA + BM * LDSR;

#pragma unroll
        for (int kk = 0; kk < 4; kk++) {
            const int kc = kk * 8 + lr;
            uint32_t a[4][4];
#pragma unroll
            for (int mf = 0; mf < 4; mf++) {
                const int r = m_base + mf * 16 + lq;
                a[mf][0] = tf32_rna_bits(sA[r * LDSR + kc]);
                a[mf][1] = tf32_rna_bits(sA[(r + 8) * LDSR + kc]);
                a[mf][2] = tf32_rna_bits(sA[r * LDSR + kc + 4]);
                a[mf][3] = tf32_rna_bits(sA[(r + 8) * LDSR + kc + 4]);
            }
            uint32_t bf[4][2];
#pragma unroll
            for (int nf = 0; nf < 4; nf++) {
                const int cn = n_base + nf * 8 + lq;
                bf[nf][0] = __float_as_uint(sB[cn * LDSR + kc]);
                bf[nf][1] = __float_as_uint(sB[cn * LDSR + kc + 4]);
            }
#pragma unroll
            for (int mf = 0; mf < 4; mf++)
#pragma unroll
                for (int nf = 0; nf < 4; nf++)
                    mma_tf32(acc[mf][nf][0], acc[mf][nf][1],
                             acc[mf][nf][2], acc[mf][nf][3],
                             a[mf][0], a[mf][1], a[mf][2], a[mf][3],
                             bf[nf][0], bf[nf][1]);
        }
        __syncthreads();
    }

    // Epilogue: registers -> global with bias. Thread (mf,nf) frag:
    // rows lq, lq+8; cols 2*lr, 2*lr+1 -> float2 stores (32B sectors / quad).
    float* outp = out + ((size_t)b * N_ + m0 + m_base) * O_ + o0 + n_base;
    const float* bp = bias + o0 + n_base;
#pragma unroll
    for (int nf = 0; nf < 4; nf++) {
        const int col = nf * 8 + lr * 2;
        const float bv0 = __ldg(bp + col);
        const float bv1 = __ldg(bp + col + 1);
#pragma unroll
        for (int mf = 0; mf < 4; mf++) {
            const int r = mf * 16 + lq;
            float2 v0 = make_float2(acc[mf][nf][0] + bv0, acc[mf][nf][1] + bv1);
            float2 v1 = make_float2(acc[mf][nf][2] + bv0, acc[mf][nf][3] + bv1);
            *reinterpret_cast<float2*>(outp + (size_t)r * O_ + col) = v0;
            *reinterpret_cast<float2*>(outp + (size_t)(r + 8) * O_ + col) = v1;
        }
    }
}

// ---------------- launch ----------------
extern "C" void kernel_launch(void* const* d_in, const int* in_sizes, int n_in,
                              void* d_out, int out_size) {
    const float* x      = (const float*)d_in[0];  // [B,N,T]
    const float* y      = (const float*)d_in[1];  // [B,G]
    const float* weight = (const float*)d_in[2];  // [G,O,T]
    const float* mask   = (const float*)d_in[3];  // [O,T]
    const float* bias   = (const float*)d_in[4];  // [O]
    float* out = (float*)d_out;                   // [B,N,O]

    mix_kernel<<<(O_ * T_ / 4) / 256, 256>>>(y, weight, mask);

    cudaFuncSetAttribute(gemm_kernel, cudaFuncAttributeMaxDynamicSharedMemorySize,
                         SMEM_BYTES);
    dim3 grid(O_ / BN, N_ / BM, B_);
    gemm_kernel<<<grid, 256, SMEM_BYTES>>>(x, bias, out);
}

// round 7
// speedup vs baseline: 1.1866x; 1.1866x over previous
#include <cuda_runtime.h>
#include <cstdint>

#define DEVINL __device__ __forceinline__

static constexpr int B_ = 32, N_ = 256, T_ = 1024, O_ = 1024, G_ = 8;

// 128 MB scratch for w_bot[b][o][t] (tf32-rounded fp32). Static __device__
// array per harness allocation rules.
__device__ float g_wbot[(size_t)B_ * O_ * T_];

// ---------------- helpers ----------------
DEVINL uint32_t smem_u32(const void* p) {
    uint32_t a;
    asm("{ .reg .u64 t; cvta.to.shared.u64 t, %1; cvt.u32.u64 %0, t; }" : "=r"(a) : "l"(p));
    return a;
}
DEVINL void cp_async16(uint32_t d, const void* g) {
    asm volatile("cp.async.cg.shared.global [%0], [%1], 16;" :: "r"(d), "l"(g) : "memory");
}
DEVINL void cp_commit() { asm volatile("cp.async.commit_group;" ::: "memory"); }
template <int NPend> DEVINL void cp_wait() {
    asm volatile("cp.async.wait_group %0;" :: "n"(NPend) : "memory");
}
DEVINL uint32_t tf32_rna_bits(float x) {
    uint32_t u;
    asm("cvt.rna.tf32.f32 %0, %1;" : "=r"(u) : "f"(x));
    return u;
}
DEVINL void mma_tf32(float& c0, float& c1, float& c2, float& c3,
                     uint32_t a0, uint32_t a1, uint32_t a2, uint32_t a3,
                     uint32_t b0, uint32_t b1) {
    asm volatile(
        "mma.sync.aligned.m16n8k8.row.col.f32.tf32.tf32.f32 "
        "{%0,%1,%2,%3}, {%4,%5,%6,%7}, {%8,%9}, {%0,%1,%2,%3};"
        : "+f"(c0), "+f"(c1), "+f"(c2), "+f"(c3)
        : "r"(a0), "r"(a1), "r"(a2), "r"(a3), "r"(b0), "r"(b1));
}

// ---------------- Pass 1: genre mixing ----------------
// w_bot[b,o,t] = sum_g y[b,g] * weight[g,o,t] * mask[o,t], rounded rna->tf32.
__global__ void __launch_bounds__(256) mix_kernel(const float* __restrict__ y,
                                                  const float* __restrict__ weight,
                                                  const float* __restrict__ mask) {
    __shared__ float ys[B_ * G_];  // 256
    const int tid = threadIdx.x;
    ys[tid] = y[tid];
    __syncthreads();

    const int idx = blockIdx.x * 256 + tid;  // over O*T/4
    const float4 mv = reinterpret_cast<const float4*>(mask)[idx];
    float4 wm[G_];
#pragma unroll
    for (int g = 0; g < G_; g++) {
        float4 w = reinterpret_cast<const float4*>(weight)[(size_t)g * (O_ * T_ / 4) + idx];
        wm[g].x = w.x * mv.x; wm[g].y = w.y * mv.y;
        wm[g].z = w.z * mv.z; wm[g].w = w.w * mv.w;
    }
    float4* wb = reinterpret_cast<float4*>(g_wbot) + idx;
#pragma unroll 4
    for (int b = 0; b < B_; b++) {
        float4 a = make_float4(0.f, 0.f, 0.f, 0.f);
#pragma unroll
        for (int g = 0; g < G_; g++) {
            const float yv = ys[b * G_ + g];
            a.x = fmaf(yv, wm[g].x, a.x);
            a.y = fmaf(yv, wm[g].y, a.y);
            a.z = fmaf(yv, wm[g].z, a.z);
            a.w = fmaf(yv, wm[g].w, a.w);
        }
        a.x = __uint_as_float(tf32_rna_bits(a.x));
        a.y = __uint_as_float(tf32_rna_bits(a.y));
        a.z = __uint_as_float(tf32_rna_bits(a.z));
        a.w = __uint_as_float(tf32_rna_bits(a.w));
        wb[(size_t)b * (O_ * T_ / 4)] = a;
    }
}

// ---------------- Pass 2: batched tf32 GEMM (mma.sync) ----------------
// out[b, m, o] = sum_t x[b,m,t] * w_bot[b,o,t] + bias[o]
// CTA tile: M=128, N=128, BK=32, 3 stages, 2 CTAs/SM (16 warps/SM).
// 8 warps: warp grid 2(m) x 4(n), warp tile 64x32. mma m16n8k8 tf32.
// A fed as raw fp32 bits (HW truncates to tf32); B pre-rounded rna in pass 1.
static constexpr int BM = 128, BN = 128, BK = 32, STAGES = 3;
static constexpr int LDSR = 36;                         // padded row: 32 + 4 floats
static constexpr int STAGE_FLOATS = (BM + BN) * LDSR;   // 9216 floats = 36 KB
static constexpr int NKT = T_ / BK;                     // 32 k-tiles
static constexpr uint32_t SMEM_BYTES = STAGES * STAGE_FLOATS * 4;  // 110592

DEVINL void load_stage(float* st, const float* __restrict__ gA,
                       const float* __restrict__ gB, int tid) {
    float* sA = st;
    float* sB = st + BM * LDSR;
#pragma unroll
    for (int i = 0; i < 4; i++) {
        const int v = tid + i * 256;
        const int row = v >> 3, c = v & 7;
        cp_async16(smem_u32(sA + row * LDSR + c * 4), gA + (size_t)row * T_ + c * 4);
    }
#pragma unroll
    for (int i = 0; i < 4; i++) {
        const int v = tid + i * 256;
        const int row = v >> 3, c = v & 7;
        cp_async16(smem_u32(sB + row * LDSR + c * 4), gB + (size_t)row * T_ + c * 4);
    }
}

__global__ void __launch_bounds__(256, 2)
gemm_kernel(const float* __restrict__ x, const float* __restrict__ bias,
            float* __restrict__ out) {
    extern __shared__ float smem[];
    const int tid = threadIdx.x;
    const int wid = tid >> 5, lane = tid & 31;
    const int lq = lane >> 2, lr = lane & 3;  // quad row, quad col
    const int wm = wid & 1, wn = wid >> 1;    // warp m (0..1), warp n (0..3)
    const int b = blockIdx.z;
    const int o0 = blockIdx.x * BN;
    const int m0 = blockIdx.y * BM;

    const float* gA = x + ((size_t)b * N_ + m0) * T_;        // [128, T]
    const float* gB = g_wbot + ((size_t)b * O_ + o0) * T_;   // [128, T]

    float acc[4][4][4];
#pragma unroll
    for (int i = 0; i < 4; i++)
#pragma unroll
        for (int j = 0; j < 4; j++)
#pragma unroll
            for (int k = 0; k < 4; k++) acc[i][j][k] = 0.f;

    // Prologue: fill stages 0..STAGES-2
#pragma unroll
    for (int s = 0; s < STAGES - 1; s++) {
        load_stage(smem + s * STAGE_FLOATS, gA + s * BK, gB + s * BK, tid);
        cp_commit();
    }

    const int m_base = wm * 64;
    const int n_base = wn * 32;

    for (int kt = 0; kt < NKT; kt++) {
        cp_wait<STAGES - 2>();
        __syncthreads();  // also protects stage slot reuse (distance = STAGES)

        // Issue next stage load (overlaps with compute below)
        if (kt + STAGES - 1 < NKT) {
            const int kn = kt + STAGES - 1;
            load_stage(smem + (kn % STAGES) * STAGE_FLOATS,
                       gA + (size_t)kn * BK, gB + (size_t)kn * BK, tid);
        }
        cp_commit();

        const float* sA = smem + (kt % STAGES) * STAGE_FLOATS;
        const float* sB = sA + BM * LDSR;

#pragma unroll
        for (int kk = 0; kk < 4; kk++) {
            const int kc = kk * 8 + lr;
            uint32_t a[4][4];
#pragma unroll
            for (int mf = 0; mf < 4; mf++) {
                const int r = m_base + mf * 16 + lq;
                a[mf][0] = __float_as_uint(sA[r * LDSR + kc]);        // HW tf32 truncation
                a[mf][1] = __float_as_uint(sA[(r + 8) * LDSR + kc]);
                a[mf][2] = __float_as_uint(sA[r * LDSR + kc + 4]);
                a[mf][3] = __float_as_uint(sA[(r + 8) * LDSR + kc + 4]);
            }
            uint32_t bf[4][2];
#pragma unroll
            for (int nf = 0; nf < 4; nf++) {
                const int cn = n_base + nf * 8 + lq;
                bf[nf][0] = __float_as_uint(sB[cn * LDSR + kc]);
                bf[nf][1] = __float_as_uint(sB[cn * LDSR + kc + 4]);
            }
#pragma unroll
            for (int mf = 0; mf < 4; mf++)
#pragma unroll
                for (int nf = 0; nf < 4; nf++)
                    mma_tf32(acc[mf][nf][0], acc[mf][nf][1],
                             acc[mf][nf][2], acc[mf][nf][3],
                             a[mf][0], a[mf][1], a[mf][2], a[mf][3],
                             bf[nf][0], bf[nf][1]);
        }
    }

    // Epilogue: registers -> global with bias (float2 stores).
    float* outp = out + ((size_t)b * N_ + m0 + m_base) * O_ + o0 + n_base;
    const float* bp = bias + o0 + n_base;
#pragma unroll
    for (int nf = 0; nf < 4; nf++) {
        const int col = nf * 8 + lr * 2;
        const float bv0 = __ldg(bp + col);
        const float bv1 = __ldg(bp + col + 1);
#pragma unroll
        for (int mf = 0; mf < 4; mf++) {
            const int r = mf * 16 + lq;
            float2 v0 = make_float2(acc[mf][nf][0] + bv0, acc[mf][nf][1] + bv1);
            float2 v1 = make_float2(acc[mf][nf][2] + bv0, acc[mf][nf][3] + bv1);
            *reinterpret_cast<float2*>(outp + (size_t)r * O_ + col) = v0;
            *reinterpret_cast<float2*>(outp + (size_t)(r + 8) * O_ + col) = v1;
        }
    }
}

// ---------------- launch ----------------
extern "C" void kernel_launch(void* const* d_in, const int* in_sizes, int n_in,
                              void* d_out, int out_size) {
    const float* x      = (const float*)d_in[0];  // [B,N,T]
    const float* y      = (const float*)d_in[1];  // [B,G]
    const float* weight = (const float*)d_in[2];  // [G,O,T]
    const float* mask   = (const float*)d_in[3];  // [O,T]
    const float* bias   = (const float*)d_in[4];  // [O]
    float* out = (float*)d_out;                   // [B,N,O]

    mix_kernel<<<(O_ * T_ / 4) / 256, 256>>>(y, weight, mask);

    cudaFuncSetAttribute(gemm_kernel, cudaFuncAttributeMaxDynamicSharedMemorySize,
                         SMEM_BYTES);
    dim3 grid(O_ / BN, N_ / BM, B_);
    gemm_kernel<<<grid, 256, SMEM_BYTES>>>(x, bias, out);
}

// round 10
// speedup vs baseline: 1.2169x; 1.0255x over previous
#include <cuda_runtime.h>
#include <cstdint>

#define DEVINL __device__ __forceinline__

static constexpr int B_ = 32, N_ = 256, T_ = 1024, O_ = 1024, G_ = 8;

// 128 MB scratch for w_bot[b][o][t] (tf32-rounded fp32). Static __device__
// array per harness allocation rules.
__device__ float g_wbot[(size_t)B_ * O_ * T_];

// ---------------- helpers ----------------
DEVINL uint32_t smem_u32(const void* p) {
    uint32_t a;
    asm("{ .reg .u64 t; cvta.to.shared.u64 t, %1; cvt.u32.u64 %0, t; }" : "=r"(a) : "l"(p));
    return a;
}
DEVINL void cp_async16(uint32_t d, const void* g) {
    asm volatile("cp.async.cg.shared.global [%0], [%1], 16;" :: "r"(d), "l"(g) : "memory");
}
DEVINL void cp_commit() { asm volatile("cp.async.commit_group;" ::: "memory"); }
template <int NPend> DEVINL void cp_wait() {
    asm volatile("cp.async.wait_group %0;" :: "n"(NPend) : "memory");
}
DEVINL uint32_t tf32_rna_bits(float x) {
    uint32_t u;
    asm("cvt.rna.tf32.f32 %0, %1;" : "=r"(u) : "f"(x));
    return u;
}
DEVINL void mma_tf32(float& c0, float& c1, float& c2, float& c3,
                     uint32_t a0, uint32_t a1, uint32_t a2, uint32_t a3,
                     uint32_t b0, uint32_t b1) {
    asm volatile(
        "mma.sync.aligned.m16n8k8.row.col.f32.tf32.tf32.f32 "
        "{%0,%1,%2,%3}, {%4,%5,%6,%7}, {%8,%9}, {%0,%1,%2,%3};"
        : "+f"(c0), "+f"(c1), "+f"(c2), "+f"(c3)
        : "r"(a0), "r"(a1), "r"(a2), "r"(a3), "r"(b0), "r"(b1));
}

// ---------------- Pass 1: genre mixing ----------------
// w_bot[b,o,t] = sum_g y[b,g] * weight[g,o,t] * mask[o,t], rounded rna->tf32.
__global__ void __launch_bounds__(256) mix_kernel(const float* __restrict__ y,
                                                  const float* __restrict__ weight,
                                                  const float* __restrict__ mask) {
    __shared__ float ys[B_ * G_];  // 256
    const int tid = threadIdx.x;
    ys[tid] = y[tid];
    __syncthreads();

    const int idx = blockIdx.x * 256 + tid;  // over O*T/4
    const float4 mv = reinterpret_cast<const float4*>(mask)[idx];
    float4 wm[G_];
#pragma unroll
    for (int g = 0; g < G_; g++) {
        float4 w = reinterpret_cast<const float4*>(weight)[(size_t)g * (O_ * T_ / 4) + idx];
        wm[g].x = w.x * mv.x; wm[g].y = w.y * mv.y;
        wm[g].z = w.z * mv.z; wm[g].w = w.w * mv.w;
    }
    float4* wb = reinterpret_cast<float4*>(g_wbot) + idx;
#pragma unroll 4
    for (int b = 0; b < B_; b++) {
        float4 a = make_float4(0.f, 0.f, 0.f, 0.f);
#pragma unroll
        for (int g = 0; g < G_; g++) {
            const float yv = ys[b * G_ + g];
            a.x = fmaf(yv, wm[g].x, a.x);
            a.y = fmaf(yv, wm[g].y, a.y);
            a.z = fmaf(yv, wm[g].z, a.z);
            a.w = fmaf(yv, wm[g].w, a.w);
        }
        a.x = __uint_as_float(tf32_rna_bits(a.x));
        a.y = __uint_as_float(tf32_rna_bits(a.y));
        a.z = __uint_as_float(tf32_rna_bits(a.z));
        a.w = __uint_as_float(tf32_rna_bits(a.w));
        wb[(size_t)b * (O_ * T_ / 4)] = a;
    }
}

// ---------------- Pass 2: batched tf32 GEMM (mma.sync) ----------------
// out[b, m, o] = sum_t x[b,m,t] * w_bot[b,o,t] + bias[o]
// CTA tile: M=128, N=128, BK=32, 3 stages, 2 CTAs/SM.
// 4 warps (128 thr): warp grid 2(m) x 2(n), warp tile 64x64 -> 32 independent
// accumulator chains per kk step (high ILP, LDS/MMA ratio 1.0).
// A fed as raw fp32 bits (HW truncates to tf32); B pre-rounded rna in pass 1.
static constexpr int BM = 128, BN = 128, BK = 32, STAGES = 3;
static constexpr int LDSR = 36;                         // padded row: 32 + 4 floats
static constexpr int STAGE_FLOATS = (BM + BN) * LDSR;   // 9216 floats = 36 KB
static constexpr int NKT = T_ / BK;                     // 32 k-tiles
static constexpr uint32_t SMEM_BYTES = STAGES * STAGE_FLOATS * 4;  // 110592

DEVINL void load_stage(float* st, const float* __restrict__ gA,
                       const float* __restrict__ gB, int tid) {
    float* sA = st;
    float* sB = st + BM * LDSR;
#pragma unroll
    for (int i = 0; i < 8; i++) {  // A: 128 rows x 8 chunks = 1024 chunks
        const int v = tid + i * 128;
        const int row = v >> 3, c = v & 7;
        cp_async16(smem_u32(sA + row * LDSR + c * 4), gA + (size_t)row * T_ + c * 4);
    }
#pragma unroll
    for (int i = 0; i < 8; i++) {
        const int v = tid + i * 128;
        const int row = v >> 3, c = v & 7;
        cp_async16(smem_u32(sB + row * LDSR + c * 4), gB + (size_t)row * T_ + c * 4);
    }
}

__global__ void __launch_bounds__(128, 2)
gemm_kernel(const float* __restrict__ x, const float* __restrict__ bias,
            float* __restrict__ out) {
    extern __shared__ float smem[];
    const int tid = threadIdx.x;
    const int wid = tid >> 5, lane = tid & 31;
    const int lq = lane >> 2, lr = lane & 3;  // quad row, quad col
    const int wm = wid & 1, wn = wid >> 1;    // warp m (0..1), warp n (0..1)
    const int b = blockIdx.z;
    const int o0 = blockIdx.x * BN;
    const int m0 = blockIdx.y * BM;

    const float* gA = x + ((size_t)b * N_ + m0) * T_;        // [128, T]
    const float* gB = g_wbot + ((size_t)b * O_ + o0) * T_;   // [128, T]

    float acc[4][8][4];
#pragma unroll
    for (int i = 0; i < 4; i++)
#pragma unroll
        for (int j = 0; j < 8; j++)
#pragma unroll
            for (int k = 0; k < 4; k++) acc[i][j][k] = 0.f;

    // Prologue: fill stages 0..STAGES-2
#pragma unroll
    for (int s = 0; s < STAGES - 1; s++) {
        load_stage(smem + s * STAGE_FLOATS, gA + s * BK, gB + s * BK, tid);
        cp_commit();
    }

    const int m_base = wm * 64;
    const int n_base = wn * 64;

    for (int kt = 0; kt < NKT; kt++) {
        cp_wait<STAGES - 2>();
        __syncthreads();  // also protects stage slot reuse (distance = STAGES)

        // Issue next stage load (overlaps with compute below)
        if (kt + STAGES - 1 < NKT) {
            const int kn = kt + STAGES - 1;
            load_stage(smem + (kn % STAGES) * STAGE_FLOATS,
                       gA + (size_t)kn * BK, gB + (size_t)kn * BK, tid);
        }
        cp_commit();

        const float* sA = smem + (kt % STAGES) * STAGE_FLOATS;
        const float* sB = sA + BM * LDSR;

#pragma unroll
        for (int kk = 0; kk < 4; kk++) {
            const int kc = kk * 8 + lr;
            uint32_t a[4][4];
#pragma unroll
            for (int mf = 0; mf < 4; mf++) {
                const int r = m_base + mf * 16 + lq;
                a[mf][0] = __float_as_uint(sA[r * LDSR + kc]);        // HW tf32 trunc
                a[mf][1] = __float_as_uint(sA[(r + 8) * LDSR + kc]);
                a[mf][2] = __float_as_uint(sA[r * LDSR + kc + 4]);
                a[mf][3] = __float_as_uint(sA[(r + 8) * LDSR + kc + 4]);
            }
            uint32_t bf[8][2];
#pragma unroll
            for (int nf = 0; nf < 8; nf++) {
                const int cn = n_base + nf * 8 + lq;
                bf[nf][0] = __float_as_uint(sB[cn * LDSR + kc]);
                bf[nf][1] = __float_as_uint(sB[cn * LDSR + kc + 4]);
            }
#pragma unroll
            for (int mf = 0; mf < 4; mf++)
#pragma unroll
                for (int nf = 0; nf < 8; nf++)
                    mma_tf32(acc[mf][nf][0], acc[mf][nf][1],
                             acc[mf][nf][2], acc[mf][nf][3],
                             a[mf][0], a[mf][1], a[mf][2], a[mf][3],
                             bf[nf][0], bf[nf][1]);
        }
    }

    // Epilogue: registers -> global with bias (float2 stores).
    float* outp = out + ((size_t)b * N_ + m0 + m_base) * O_ + o0 + n_base;
    const float* bp = bias + o0 + n_base;
#pragma unroll
    for (int nf = 0; nf < 8; nf++) {
        const int col = nf * 8 + lr * 2;
        const float bv0 = __ldg(bp + col);
        const float bv1 = __ldg(bp + col + 1);
#pragma unroll
        for (int mf = 0; mf < 4; mf++) {
            const int r = mf * 16 + lq;
            float2 v0 = make_float2(acc[mf][nf][0] + bv0, acc[mf][nf][1] + bv1);
            float2 v1 = make_float2(acc[mf][nf][2] + bv0, acc[mf][nf][3] + bv1);
            *reinterpret_cast<float2*>(outp + (size_t)r * O_ + col) = v0;
            *reinterpret_cast<float2*>(outp + (size_t)(r + 8) * O_ + col) = v1;
        }
    }
}

// ---------------- launch ----------------
extern "C" void kernel_launch(void* const* d_in, const int* in_sizes, int n_in,
                              void* d_out, int out_size) {
    const float* x      = (const float*)d_in[0];  // [B,N,T]
    const float* y      = (const float*)d_in[1];  // [B,G]
    const float* weight = (const float*)d_in[2];  // [G,O,T]
    const float* mask   = (const float*)d_in[3];  // [O,T]
    const float* bias   = (const float*)d_in[4];  // [O]
    float* out = (float*)d_out;                   // [B,N,O]

    mix_kernel<<<(O_ * T_ / 4) / 256, 256>>>(y, weight, mask);

    cudaFuncSetAttribute(gemm_kernel, cudaFuncAttributeMaxDynamicSharedMemorySize,
                         SMEM_BYTES);
    dim3 grid(O_ / BN, N_ / BM, B_);
    gemm_kernel<<<grid, 128, SMEM_BYTES>>>(x, bias, out);
}

// round 11
// speedup vs baseline: 1.2727x; 1.0459x over previous
#include <cuda_runtime.h>
#include <cstdint>

#define DEVINL __device__ __forceinline__

static constexpr int B_ = 32, N_ = 256, T_ = 1024, O_ = 1024, G_ = 8;

// 128 MB scratch for w_bot[b][o][t] (tf32-rounded fp32). Static __device__
// array per harness allocation rules.
__device__ float g_wbot[(size_t)B_ * O_ * T_];

// ---------------- helpers ----------------
DEVINL uint32_t smem_u32(const void* p) {
    uint32_t a;
    asm("{ .reg .u64 t; cvta.to.shared.u64 t, %1; cvt.u32.u64 %0, t; }" : "=r"(a) : "l"(p));
    return a;
}
DEVINL void cp_async16(uint32_t d, const void* g) {
    asm volatile("cp.async.cg.shared.global [%0], [%1], 16;" :: "r"(d), "l"(g) : "memory");
}
DEVINL void cp_commit() { asm volatile("cp.async.commit_group;" ::: "memory"); }
template <int NPend> DEVINL void cp_wait() {
    asm volatile("cp.async.wait_group %0;" :: "n"(NPend) : "memory");
}
DEVINL uint32_t tf32_rna_bits(float x) {
    uint32_t u;
    asm("cvt.rna.tf32.f32 %0, %1;" : "=r"(u) : "f"(x));
    return u;
}
// ldmatrix x4 on 32-bit data: each thread gets 4 consecutive bytes of a tile
// row, so tf32 elements are moved intact (no .trans anywhere).
DEVINL void ldsm_x4(uint32_t& r0, uint32_t& r1, uint32_t& r2, uint32_t& r3,
                    uint32_t addr) {
    asm volatile("ldmatrix.sync.aligned.m8n8.x4.shared.b16 {%0,%1,%2,%3}, [%4];"
                 : "=r"(r0), "=r"(r1), "=r"(r2), "=r"(r3) : "r"(addr));
}
DEVINL void mma_tf32(float& c0, float& c1, float& c2, float& c3,
                     uint32_t a0, uint32_t a1, uint32_t a2, uint32_t a3,
                     uint32_t b0, uint32_t b1) {
    asm volatile(
        "mma.sync.aligned.m16n8k8.row.col.f32.tf32.tf32.f32 "
        "{%0,%1,%2,%3}, {%4,%5,%6,%7}, {%8,%9}, {%0,%1,%2,%3};"
        : "+f"(c0), "+f"(c1), "+f"(c2), "+f"(c3)
        : "r"(a0), "r"(a1), "r"(a2), "r"(a3), "r"(b0), "r"(b1));
}

// ---------------- Pass 1: genre mixing ----------------
// w_bot[b,o,t] = sum_g y[b,g] * weight[g,o,t] * mask[o,t], rounded rna->tf32.
__global__ void __launch_bounds__(256) mix_kernel(const float* __restrict__ y,
                                                  const float* __restrict__ weight,
                                                  const float* __restrict__ mask) {
    __shared__ float ys[B_ * G_];  // 256
    const int tid = threadIdx.x;
    ys[tid] = y[tid];
    __syncthreads();

    const int idx = blockIdx.x * 256 + tid;  // over O*T/4
    const float4 mv = reinterpret_cast<const float4*>(mask)[idx];
    float4 wm[G_];
#pragma unroll
    for (int g = 0; g < G_; g++) {
        float4 w = reinterpret_cast<const float4*>(weight)[(size_t)g * (O_ * T_ / 4) + idx];
        wm[g].x = w.x * mv.x; wm[g].y = w.y * mv.y;
        wm[g].z = w.z * mv.z; wm[g].w = w.w * mv.w;
    }
    float4* wb = reinterpret_cast<float4*>(g_wbot) + idx;
#pragma unroll 4
    for (int b = 0; b < B_; b++) {
        float4 a = make_float4(0.f, 0.f, 0.f, 0.f);
#pragma unroll
        for (int g = 0; g < G_; g++) {
            const float yv = ys[b * G_ + g];
            a.x = fmaf(yv, wm[g].x, a.x);
            a.y = fmaf(yv, wm[g].y, a.y);
            a.z = fmaf(yv, wm[g].z, a.z);
            a.w = fmaf(yv, wm[g].w, a.w);
        }
        a.x = __uint_as_float(tf32_rna_bits(a.x));
        a.y = __uint_as_float(tf32_rna_bits(a.y));
        a.z = __uint_as_float(tf32_rna_bits(a.z));
        a.w = __uint_as_float(tf32_rna_bits(a.w));
        wb[(size_t)b * (O_ * T_ / 4)] = a;
    }
}

// ---------------- Pass 2: batched tf32 GEMM (mma.sync + ldmatrix) ----------
// out[b, m, o] = sum_t x[b,m,t] * w_bot[b,o,t] + bias[o]
// CTA tile: M=128, N=128, BK=32, 3 stages, 2 CTAs/SM.
// 4 warps: warp grid 2(m) x 2(n), warp tile 64x64.
// Fragments via ldmatrix.x4 (8 LDSM per kk instead of 32 scalar LDS).
// A fed as raw fp32 bits (HW truncates to tf32); B pre-rounded rna in pass 1.
static constexpr int BM = 128, BN = 128, BK = 32, STAGES = 3;
static constexpr int LDSR = 36;                         // padded row: 32 + 4 floats
static constexpr int STAGE_FLOATS = (BM + BN) * LDSR;   // 9216 floats = 36 KB
static constexpr int NKT = T_ / BK;                     // 32 k-tiles
static constexpr uint32_t SMEM_BYTES = STAGES * STAGE_FLOATS * 4;  // 110592

DEVINL void load_stage(float* st, const float* __restrict__ gA,
                       const float* __restrict__ gB, int tid) {
    float* sA = st;
    float* sB = st + BM * LDSR;
#pragma unroll
    for (int i = 0; i < 8; i++) {  // A: 128 rows x 8 chunks = 1024 chunks
        const int v = tid + i * 128;
        const int row = v >> 3, c = v & 7;
        cp_async16(smem_u32(sA + row * LDSR + c * 4), gA + (size_t)row * T_ + c * 4);
    }
#pragma unroll
    for (int i = 0; i < 8; i++) {
        const int v = tid + i * 128;
        const int row = v >> 3, c = v & 7;
        cp_async16(smem_u32(sB + row * LDSR + c * 4), gB + (size_t)row * T_ + c * 4);
    }
}

__global__ void __launch_bounds__(128, 2)
gemm_kernel(const float* __restrict__ x, const float* __restrict__ bias,
            float* __restrict__ out) {
    extern __shared__ float smem[];
    const uint32_t sbase = smem_u32(smem);
    const int tid = threadIdx.x;
    const int wid = tid >> 5, lane = tid & 31;
    const int lq = lane >> 2, lr = lane & 3;  // quad row, quad col (epilogue)
    const int wm = wid & 1, wn = wid >> 1;    // warp m (0..1), warp n (0..1)
    const int b = blockIdx.z;
    const int o0 = blockIdx.x * BN;
    const int m0 = blockIdx.y * BM;

    const float* gA = x + ((size_t)b * N_ + m0) * T_;        // [128, T]
    const float* gB = g_wbot + ((size_t)b * O_ + o0) * T_;   // [128, T]

    const int m_base = wm * 64;
    const int n_base = wn * 64;

    // ldmatrix per-lane source coordinates (tile j = lane>>3, row i = lane&7):
    // A x4 tiles for (mf,kk): j&1 -> +8 rows, j>>1 -> +4 k.
    const int aRow = m_base + ((lane >> 3) & 1) * 8 + (lane & 7);
    const int aK   = (lane >> 4) * 4;
    // B x4 tiles for nf-pair: j&1 -> +4 k, j>>1 -> +8 n-rows.
    const int bRow = n_base + (lane >> 4) * 8 + (lane & 7);
    const int bK   = ((lane >> 3) & 1) * 4;
    const uint32_t aOff = (uint32_t)(aRow * LDSR + aK) * 4u;
    const uint32_t bOff = (uint32_t)(BM * LDSR + bRow * LDSR + bK) * 4u;

    float acc[4][8][4];
#pragma unroll
    for (int i = 0; i < 4; i++)
#pragma unroll
        for (int j = 0; j < 8; j++)
#pragma unroll
            for (int k = 0; k < 4; k++) acc[i][j][k] = 0.f;

    // Prologue: fill stages 0..STAGES-2
#pragma unroll
    for (int s = 0; s < STAGES - 1; s++) {
        load_stage(smem + s * STAGE_FLOATS, gA + s * BK, gB + s * BK, tid);
        cp_commit();
    }

    for (int kt = 0; kt < NKT; kt++) {
        cp_wait<STAGES - 2>();
        __syncthreads();  // also protects stage slot reuse (distance = STAGES)

        // Issue next stage load (overlaps with compute below)
        if (kt + STAGES - 1 < NKT) {
            const int kn = kt + STAGES - 1;
            load_stage(smem + (kn % STAGES) * STAGE_FLOATS,
                       gA + (size_t)kn * BK, gB + (size_t)kn * BK, tid);
        }
        cp_commit();

        const uint32_t stg = sbase + (uint32_t)((kt % STAGES) * STAGE_FLOATS) * 4u;
        const uint32_t aBase = stg + aOff;
        const uint32_t bBase = stg + bOff;

#pragma unroll
        for (int kk = 0; kk < 4; kk++) {
            uint32_t a[4][4];
#pragma unroll
            for (int mf = 0; mf < 4; mf++)
                ldsm_x4(a[mf][0], a[mf][1], a[mf][2], a[mf][3],
                        aBase + (uint32_t)(mf * 16 * LDSR + kk * 8) * 4u);
            uint32_t bf[8][2];
#pragma unroll
            for (int nfp = 0; nfp < 4; nfp++)
                ldsm_x4(bf[2 * nfp][0], bf[2 * nfp][1],
                        bf[2 * nfp + 1][0], bf[2 * nfp + 1][1],
                        bBase + (uint32_t)(nfp * 16 * LDSR + kk * 8) * 4u);
#pragma unroll
            for (int mf = 0; mf < 4; mf++)
#pragma unroll
                for (int nf = 0; nf < 8; nf++)
                    mma_tf32(acc[mf][nf][0], acc[mf][nf][1],
                             acc[mf][nf][2], acc[mf][nf][3],
                             a[mf][0], a[mf][1], a[mf][2], a[mf][3],
                             bf[nf][0], bf[nf][1]);
        }
    }

    // Epilogue: registers -> global with bias (float2 stores).
    float* outp = out + ((size_t)b * N_ + m0 + m_base) * O_ + o0 + n_base;
    const float* bp = bias + o0 + n_base;
#pragma unroll
    for (int nf = 0; nf < 8; nf++) {
        const int col = nf * 8 + lr * 2;
        const float bv0 = __ldg(bp + col);
        const float bv1 = __ldg(bp + col + 1);
#pragma unroll
        for (int mf = 0; mf < 4; mf++) {
            const int r = mf * 16 + lq;
            float2 v0 = make_float2(acc[mf][nf][0] + bv0, acc[mf][nf][1] + bv1);
            float2 v1 = make_float2(acc[mf][nf][2] + bv0, acc[mf][nf][3] + bv1);
            *reinterpret_cast<float2*>(outp + (size_t)r * O_ + col) = v0;
            *reinterpret_cast<float2*>(outp + (size_t)(r + 8) * O_ + col) = v1;
        }
    }
}

// ---------------- launch ----------------
extern "C" void kernel_launch(void* const* d_in, const int* in_sizes, int n_in,
                              void* d_out, int out_size) {
    const float* x      = (const float*)d_in[0];  // [B,N,T]
    const float* y      = (const float*)d_in[1];  // [B,G]
    const float* weight = (const float*)d_in[2];  // [G,O,T]
    const float* mask   = (const float*)d_in[3];  // [O,T]
    const float* bias   = (const float*)d_in[4];  // [O]
    float* out = (float*)d_out;                   // [B,N,O]

    mix_kernel<<<(O_ * T_ / 4) / 256, 256>>>(y, weight, mask);

    cudaFuncSetAttribute(gemm_kernel, cudaFuncAttributeMaxDynamicSharedMemorySize,
                         SMEM_BYTES);
    dim3 grid(O_ / BN, N_ / BM, B_);
    gemm_kernel<<<grid, 128, SMEM_BYTES>>>(x, bias, out);
}

// round 12
// speedup vs baseline: 1.2739x; 1.0009x over previous
#include <cuda_runtime.h>
#include <cstdint>

#define DEVINL __device__ __forceinline__

static constexpr int B_ = 32, N_ = 256, T_ = 1024, O_ = 1024, G_ = 8;

// 128 MB scratch for w_bot[b][o][t] (tf32-rounded fp32). Static __device__
// array per harness allocation rules.
__device__ float g_wbot[(size_t)B_ * O_ * T_];

// ---------------- helpers ----------------
DEVINL uint32_t smem_u32(const void* p) {
    uint32_t a;
    asm("{ .reg .u64 t; cvta.to.shared.u64 t, %1; cvt.u32.u64 %0, t; }" : "=r"(a) : "l"(p));
    return a;
}
DEVINL void cp_async16(uint32_t d, const void* g) {
    asm volatile("cp.async.cg.shared.global [%0], [%1], 16;" :: "r"(d), "l"(g) : "memory");
}
DEVINL void cp_commit() { asm volatile("cp.async.commit_group;" ::: "memory"); }
template <int NPend> DEVINL void cp_wait() {
    asm volatile("cp.async.wait_group %0;" :: "n"(NPend) : "memory");
}
DEVINL uint32_t tf32_rna_bits(float x) {
    uint32_t u;
    asm("cvt.rna.tf32.f32 %0, %1;" : "=r"(u) : "f"(x));
    return u;
}
// ldmatrix x4 on 32-bit data: each thread gets 4 consecutive bytes of a tile
// row, so tf32 elements are moved intact (no .trans anywhere).
DEVINL void ldsm_x4(uint32_t& r0, uint32_t& r1, uint32_t& r2, uint32_t& r3,
                    uint32_t addr) {
    asm volatile("ldmatrix.sync.aligned.m8n8.x4.shared.b16 {%0,%1,%2,%3}, [%4];"
                 : "=r"(r0), "=r"(r1), "=r"(r2), "=r"(r3) : "r"(addr));
}
DEVINL void mma_tf32(float& c0, float& c1, float& c2, float& c3,
                     uint32_t a0, uint32_t a1, uint32_t a2, uint32_t a3,
                     uint32_t b0, uint32_t b1) {
    asm volatile(
        "mma.sync.aligned.m16n8k8.row.col.f32.tf32.tf32.f32 "
        "{%0,%1,%2,%3}, {%4,%5,%6,%7}, {%8,%9}, {%0,%1,%2,%3};"
        : "+f"(c0), "+f"(c1), "+f"(c2), "+f"(c3)
        : "r"(a0), "r"(a1), "r"(a2), "r"(a3), "r"(b0), "r"(b1));
}

// ---------------- Pass 1: genre mixing ----------------
// w_bot[b,o,t] = sum_g y[b,g] * weight[g,o,t] * mask[o,t], rounded rna->tf32.
__global__ void __launch_bounds__(256) mix_kernel(const float* __restrict__ y,
                                                  const float* __restrict__ weight,
                                                  const float* __restrict__ mask) {
    __shared__ float ys[B_ * G_];  // 256
    const int tid = threadIdx.x;
    ys[tid] = y[tid];
    __syncthreads();

    const int idx = blockIdx.x * 256 + tid;  // over O*T/4
    const float4 mv = reinterpret_cast<const float4*>(mask)[idx];
    float4 wm[G_];
#pragma unroll
    for (int g = 0; g < G_; g++) {
        float4 w = reinterpret_cast<const float4*>(weight)[(size_t)g * (O_ * T_ / 4) + idx];
        wm[g].x = w.x * mv.x; wm[g].y = w.y * mv.y;
        wm[g].z = w.z * mv.z; wm[g].w = w.w * mv.w;
    }
    float4* wb = reinterpret_cast<float4*>(g_wbot) + idx;
#pragma unroll 4
    for (int b = 0; b < B_; b++) {
        float4 a = make_float4(0.f, 0.f, 0.f, 0.f);
#pragma unroll
        for (int g = 0; g < G_; g++) {
            const float yv = ys[b * G_ + g];
            a.x = fmaf(yv, wm[g].x, a.x);
            a.y = fmaf(yv, wm[g].y, a.y);
            a.z = fmaf(yv, wm[g].z, a.z);
            a.w = fmaf(yv, wm[g].w, a.w);
        }
        a.x = __uint_as_float(tf32_rna_bits(a.x));
        a.y = __uint_as_float(tf32_rna_bits(a.y));
        a.z = __uint_as_float(tf32_rna_bits(a.z));
        a.w = __uint_as_float(tf32_rna_bits(a.w));
        wb[(size_t)b * (O_ * T_ / 4)] = a;
    }
}

// ---------------- Pass 2: batched tf32 GEMM (mma.sync + ldmatrix) ----------
// out[b, m, o] = sum_t x[b,m,t] * w_bot[b,o,t] + bias[o]
// CTA tile: M=128, N=128, BK=32, 3 stages, 2 CTAs/SM.
// 4 warps: warp grid 2(m) x 2(n), warp tile 64x64.
// Fragments double-buffered in registers across kk steps: LDSM for kk+1
// issues before the 32 MMAs of kk, hiding LDS latency under tensor issue.
// A fed as raw fp32 bits (HW truncates to tf32); B pre-rounded rna in pass 1.
static constexpr int BM = 128, BN = 128, BK = 32, STAGES = 3;
static constexpr int LDSR = 36;                         // padded row: 32 + 4 floats
static constexpr int STAGE_FLOATS = (BM + BN) * LDSR;   // 9216 floats = 36 KB
static constexpr int NKT = T_ / BK;                     // 32 k-tiles
static constexpr uint32_t SMEM_BYTES = STAGES * STAGE_FLOATS * 4;  // 110592

DEVINL void load_stage(float* st, const float* __restrict__ gA,
                       const float* __restrict__ gB, int tid) {
    float* sA = st;
    float* sB = st + BM * LDSR;
#pragma unroll
    for (int i = 0; i < 8; i++) {  // A: 128 rows x 8 chunks = 1024 chunks
        const int v = tid + i * 128;
        const int row = v >> 3, c = v & 7;
        cp_async16(smem_u32(sA + row * LDSR + c * 4), gA + (size_t)row * T_ + c * 4);
    }
#pragma unroll
    for (int i = 0; i < 8; i++) {
        const int v = tid + i * 128;
        const int row = v >> 3, c = v & 7;
        cp_async16(smem_u32(sB + row * LDSR + c * 4), gB + (size_t)row * T_ + c * 4);
    }
}

__global__ void __launch_bounds__(128, 2)
gemm_kernel(const float* __restrict__ x, const float* __restrict__ bias,
            float* __restrict__ out) {
    extern __shared__ float smem[];
    const uint32_t sbase = smem_u32(smem);
    const int tid = threadIdx.x;
    const int wid = tid >> 5, lane = tid & 31;
    const int lq = lane >> 2, lr = lane & 3;  // quad row, quad col (epilogue)
    const int wm = wid & 1, wn = wid >> 1;    // warp m (0..1), warp n (0..1)
    const int b = blockIdx.z;
    const int o0 = blockIdx.x * BN;
    const int m0 = blockIdx.y * BM;

    const float* gA = x + ((size_t)b * N_ + m0) * T_;        // [128, T]
    const float* gB = g_wbot + ((size_t)b * O_ + o0) * T_;   // [128, T]

    const int m_base = wm * 64;
    const int n_base = wn * 64;

    // ldmatrix per-lane source coordinates (tile j = lane>>3, row i = lane&7):
    // A x4 tiles for (mf,kk): j&1 -> +8 rows, j>>1 -> +4 k.
    const int aRow = m_base + ((lane >> 3) & 1) * 8 + (lane & 7);
    const int aK   = (lane >> 4) * 4;
    // B x4 tiles for nf-pair: j&1 -> +4 k, j>>1 -> +8 n-rows.
    const int bRow = n_base + (lane >> 4) * 8 + (lane & 7);
    const int bK   = ((lane >> 3) & 1) * 4;
    const uint32_t aOff = (uint32_t)(aRow * LDSR + aK) * 4u;
    const uint32_t bOff = (uint32_t)(BM * LDSR + bRow * LDSR + bK) * 4u;

    float acc[4][8][4];
#pragma unroll
    for (int i = 0; i < 4; i++)
#pragma unroll
        for (int j = 0; j < 8; j++)
#pragma unroll
            for (int k = 0; k < 4; k++) acc[i][j][k] = 0.f;

    // Prologue: fill stages 0..STAGES-2
#pragma unroll
    for (int s = 0; s < STAGES - 1; s++) {
        load_stage(smem + s * STAGE_FLOATS, gA + s * BK, gB + s * BK, tid);
        cp_commit();
    }

    uint32_t a[2][4][4];   // double-buffered A fragments
    uint32_t bf[2][8][2];  // double-buffered B fragments

    for (int kt = 0; kt < NKT; kt++) {
        cp_wait<STAGES - 2>();
        __syncthreads();  // also protects stage slot reuse (distance = STAGES)

        const uint32_t stg = sbase + (uint32_t)((kt % STAGES) * STAGE_FLOATS) * 4u;
        const uint32_t aBase = stg + aOff;
        const uint32_t bBase = stg + bOff;

        // Prefetch fragments for kk=0 into buffer 0
#pragma unroll
        for (int mf = 0; mf < 4; mf++)
            ldsm_x4(a[0][mf][0], a[0][mf][1], a[0][mf][2], a[0][mf][3],
                    aBase + (uint32_t)(mf * 16 * LDSR) * 4u);
#pragma unroll
        for (int nfp = 0; nfp < 4; nfp++)
            ldsm_x4(bf[0][2 * nfp][0], bf[0][2 * nfp][1],
                    bf[0][2 * nfp + 1][0], bf[0][2 * nfp + 1][1],
                    bBase + (uint32_t)(nfp * 16 * LDSR) * 4u);

        // Issue next stage global loads (overlap with MMAs below)
        if (kt + STAGES - 1 < NKT) {
            const int kn = kt + STAGES - 1;
            load_stage(smem + (kn % STAGES) * STAGE_FLOATS,
                       gA + (size_t)kn * BK, gB + (size_t)kn * BK, tid);
        }
        cp_commit();

#pragma unroll
        for (int kk = 0; kk < 4; kk++) {
            const int cur = kk & 1, nxt = cur ^ 1;
            if (kk < 3) {  // prefetch kk+1 fragments before this kk's MMAs
                const uint32_t ko = (uint32_t)((kk + 1) * 8) * 4u;
#pragma unroll
                for (int mf = 0; mf < 4; mf++)
                    ldsm_x4(a[nxt][mf][0], a[nxt][mf][1], a[nxt][mf][2], a[nxt][mf][3],
                            aBase + (uint32_t)(mf * 16 * LDSR) * 4u + ko);
#pragma unroll
                for (int nfp = 0; nfp < 4; nfp++)
                    ldsm_x4(bf[nxt][2 * nfp][0], bf[nxt][2 * nfp][1],
                            bf[nxt][2 * nfp + 1][0], bf[nxt][2 * nfp + 1][1],
                            bBase + (uint32_t)(nfp * 16 * LDSR) * 4u + ko);
            }
#pragma unroll
            for (int mf = 0; mf < 4; mf++)
#pragma unroll
                for (int nf = 0; nf < 8; nf++)
                    mma_tf32(acc[mf][nf][0], acc[mf][nf][1],
                             acc[mf][nf][2], acc[mf][nf][3],
                             a[cur][mf][0], a[cur][mf][1], a[cur][mf][2], a[cur][mf][3],
                             bf[cur][nf][0], bf[cur][nf][1]);
        }
    }

    // Epilogue: registers -> global with bias (float2 stores).
    float* outp = out + ((size_t)b * N_ + m0 + m_base) * O_ + o0 + n_base;
    const float* bp = bias + o0 + n_base;
#pragma unroll
    for (int nf = 0; nf < 8; nf++) {
        const int col = nf * 8 + lr * 2;
        const float bv0 = __ldg(bp + col);
        const float bv1 = __ldg(bp + col + 1);
#pragma unroll
        for (int mf = 0; mf < 4; mf++) {
            const int r = mf * 16 + lq;
            float2 v0 = make_float2(acc[mf][nf][0] + bv0, acc[mf][nf][1] + bv1);
            float2 v1 = make_float2(acc[mf][nf][2] + bv0, acc[mf][nf][3] + bv1);
            *reinterpret_cast<float2*>(outp + (size_t)r * O_ + col) = v0;
            *reinterpret_cast<float2*>(outp + (size_t)(r + 8) * O_ + col) = v1;
        }
    }
}

// ---------------- launch ----------------
extern "C" void kernel_launch(void* const* d_in, const int* in_sizes, int n_in,
                              void* d_out, int out_size) {
    const float* x      = (const float*)d_in[0];  // [B,N,T]
    const float* y      = (const float*)d_in[1];  // [B,G]
    const float* weight = (const float*)d_in[2];  // [G,O,T]
    const float* mask   = (const float*)d_in[3];  // [O,T]
    const float* bias   = (const float*)d_in[4];  // [O]
    float* out = (float*)d_out;                   // [B,N,O]

    mix_kernel<<<(O_ * T_ / 4) / 256, 256>>>(y, weight, mask);

    cudaFuncSetAttribute(gemm_kernel, cudaFuncAttributeMaxDynamicSharedMemorySize,
                         SMEM_BYTES);
    dim3 grid(O_ / BN, N_ / BM, B_);
    gemm_kernel<<<grid, 128, SMEM_BYTES>>>(x, bias, out);
}